// round 7
// baseline (speedup 1.0000x reference)
#include <cuda_runtime.h>
#include <math.h>

#define NJ     14
#define ELEM   (NJ * 3)     // 42 floats per element per tensor
#define TPB    128
#define EPB    (TPB / 2)    // 64 elements per block (2 lanes per element)
#define ROW    45           // padded smem row per element
#define JH     7            // joints per lane (half)

__device__ __forceinline__ float fast_sqrt(float x) {
    return x * rsqrtf(x + 1e-30f);
}

// Branchless Jacobi rotation, 2 MUFUs deep, division-free.
__device__ __forceinline__ void jacobi_rot(float A[3][3], float V[3][3], int p, int q) {
    float apq = A[p][q];
    float app = A[p][p], aqq = A[q][q];
    float h = aqq - app;
    float w = rsqrtf(h * h + 4.0f * apq * apq + 1e-38f);
    float sgn = copysignf(1.0f, h);
    float cos2t = fminf(fabsf(h) * w, 1.0f);
    float sin2t = 2.0f * apq * w * sgn;
    float c2 = 0.5f * (1.0f + cos2t);
    float invc = rsqrtf(c2);
    float c = c2 * invc;
    float s = 0.5f * sin2t * invc;
    int r = 3 - p - q;
    float arp = A[r][p], arq = A[r][q];
    float narp = c * arp - s * arq;
    float narq = s * arp + c * arq;
    A[r][p] = narp; A[p][r] = narp;
    A[r][q] = narq; A[q][r] = narq;
    float napp = c * c * app - 2.0f * s * c * apq + s * s * aqq;
    float naqq = s * s * app + 2.0f * s * c * apq + c * c * aqq;
    A[p][p] = napp; A[q][q] = naqq;
    A[p][q] = 0.0f; A[q][p] = 0.0f;
#pragma unroll
    for (int i = 0; i < 3; i++) {
        float vip = V[i][p], viq = V[i][q];
        V[i][p] = c * vip - s * viq;
        V[i][q] = s * vip + c * viq;
    }
}

__device__ __forceinline__ float pair_sum(float v) {
    return v + __shfl_xor_sync(0xFFFFFFFFu, v, 1);
}

__global__ void __launch_bounds__(TPB, 8)
pampjpe_kernel(const float* __restrict__ pred,
               const float* __restrict__ gt,
               float* __restrict__ out, int B)
{
    __shared__ float sp[EPB * ROW];
    __shared__ float sg[EPB * ROW];

    const int base = blockIdx.x * EPB;
    const int tid  = threadIdx.x;
    const int valid = min(EPB, B - base);          // elements in this block
    const int total = valid * ELEM;

    const float* __restrict__ pbase = pred + (size_t)base * ELEM;
    const float* __restrict__ gbase = gt   + (size_t)base * ELEM;

    if (valid == EPB) {
        const int total4 = (EPB * ELEM) / 4;       // 672 float4 per tensor
        const float4* __restrict__ p4 = (const float4*)pbase;
        const float4* __restrict__ g4 = (const float4*)gbase;
#pragma unroll 3
        for (int i4 = tid; i4 < total4; i4 += TPB) {
            float4 vp = p4[i4];
            float4 vg = g4[i4];
            int idx = i4 * 4;
            float ap[4] = {vp.x, vp.y, vp.z, vp.w};
            float ag[4] = {vg.x, vg.y, vg.z, vg.w};
#pragma unroll
            for (int c = 0; c < 4; c++) {
                int id = idx + c;
                int e = id / ELEM;
                int k = id - e * ELEM;
                sp[e * ROW + k] = ap[c];
                sg[e * ROW + k] = ag[c];
            }
        }
    } else {
        for (int i = tid; i < total; i += TPB) {
            int e = i / ELEM;
            int k = i - e * ELEM;
            sp[e * ROW + k] = pbase[i];
            sg[e * ROW + k] = gbase[i];
        }
    }
    __syncthreads();

    // Two lanes (tid, tid^1) share element e; each handles 7 joints.
    const int e    = tid >> 1;
    const int half = tid & 1;
    const float* P = &sp[e * ROW + half * (JH * 3)];
    const float* G = &sg[e * ROW + half * (JH * 3)];

    // Partial means over my 7 joints, then pair-combine
    float mu1[3] = {0.f, 0.f, 0.f};
    float mu2[3] = {0.f, 0.f, 0.f};
#pragma unroll
    for (int j = 0; j < JH; j++) {
#pragma unroll
        for (int a = 0; a < 3; a++) {
            mu1[a] += P[j * 3 + a];
            mu2[a] += G[j * 3 + a];
        }
    }
    const float invJ = 1.0f / (float)NJ;
#pragma unroll
    for (int a = 0; a < 3; a++) {
        mu1[a] = pair_sum(mu1[a]) * invJ;
        mu2[a] = pair_sum(mu2[a]) * invJ;
    }

    // Partial cross-covariance + var1 over my 7 joints, then pair-combine
    float K[3][3] = {{0}};
    float var1 = 0.f;
#pragma unroll
    for (int j = 0; j < JH; j++) {
        float x[3], y[3];
#pragma unroll
        for (int a = 0; a < 3; a++) {
            x[a] = P[j * 3 + a] - mu1[a];
            y[a] = G[j * 3 + a] - mu2[a];
            var1 += x[a] * x[a];
        }
#pragma unroll
        for (int a = 0; a < 3; a++)
#pragma unroll
            for (int b = 0; b < 3; b++)
                K[a][b] += x[a] * y[b];
    }
#pragma unroll
    for (int a = 0; a < 3; a++)
#pragma unroll
        for (int b = 0; b < 3; b++)
            K[a][b] = pair_sum(K[a][b]);
    var1 = pair_sum(var1);

    // ---- solve (run redundantly on both lanes; identical inputs) ----
    // A = K^T K (symmetric)
    float A[3][3];
#pragma unroll
    for (int i = 0; i < 3; i++)
#pragma unroll
        for (int j = i; j < 3; j++) {
            float acc = 0.f;
#pragma unroll
            for (int k = 0; k < 3; k++) acc += K[k][i] * K[k][j];
            A[i][j] = acc; A[j][i] = acc;
        }

    float V[3][3] = {{1.f, 0.f, 0.f}, {0.f, 1.f, 0.f}, {0.f, 0.f, 1.f}};
#pragma unroll
    for (int sweep = 0; sweep < 3; sweep++) {
        jacobi_rot(A, V, 0, 1);
        jacobi_rot(A, V, 0, 2);
        jacobi_rot(A, V, 1, 2);
    }

    float lam[3] = {A[0][0], A[1][1], A[2][2]};
#pragma unroll
    for (int a = 0; a < 2; a++)
#pragma unroll
        for (int b = a + 1; b < 3; b++)
            if (lam[a] < lam[b]) {
                float tl = lam[a]; lam[a] = lam[b]; lam[b] = tl;
#pragma unroll
                for (int r = 0; r < 3; r++) {
                    float tv = V[r][a]; V[r][a] = V[r][b]; V[r][b] = tv;
                }
            }

    float v0[3] = {V[0][0], V[1][0], V[2][0]};
    float v1[3] = {V[0][1], V[1][1], V[2][1]};
    float v2[3] = {v0[1]*v1[2] - v0[2]*v1[1],
                   v0[2]*v1[0] - v0[0]*v1[2],
                   v0[0]*v1[1] - v0[1]*v1[0]};

    float u0[3], u1[3];
#pragma unroll
    for (int i = 0; i < 3; i++) {
        u0[i] = K[i][0]*v0[0] + K[i][1]*v0[1] + K[i][2]*v0[2];
        u1[i] = K[i][0]*v1[0] + K[i][1]*v1[1] + K[i][2]*v1[2];
    }
    float n0 = rsqrtf(u0[0]*u0[0] + u0[1]*u0[1] + u0[2]*u0[2] + 1e-30f);
#pragma unroll
    for (int i = 0; i < 3; i++) u0[i] *= n0;
    float dot01 = u0[0]*u1[0] + u0[1]*u1[1] + u0[2]*u1[2];
#pragma unroll
    for (int i = 0; i < 3; i++) u1[i] -= dot01 * u0[i];
    float n1 = rsqrtf(u1[0]*u1[0] + u1[1]*u1[1] + u1[2]*u1[2] + 1e-30f);
#pragma unroll
    for (int i = 0; i < 3; i++) u1[i] *= n1;
    float u2[3] = {u0[1]*u1[2] - u0[2]*u1[1],
                   u0[2]*u1[0] - u0[0]*u1[2],
                   u0[0]*u1[1] - u0[1]*u1[0]};

    float R[3][3];
#pragma unroll
    for (int i = 0; i < 3; i++)
#pragma unroll
        for (int j = 0; j < 3; j++)
            R[i][j] = v0[i]*u0[j] + v1[i]*u1[j] + v2[i]*u2[j];

    float trRK = 0.f;
#pragma unroll
    for (int i = 0; i < 3; i++)
#pragma unroll
        for (int k = 0; k < 3; k++)
            trRK += R[i][k] * K[k][i];
    float scale = __fdividef(trRK, var1 + 1e-30f);

    // Per-joint error over my 7 joints, pair-combine, even lane writes
    float acc = 0.f;
#pragma unroll
    for (int j = 0; j < JH; j++) {
        float x[3], y[3];
#pragma unroll
        for (int a = 0; a < 3; a++) {
            x[a] = P[j * 3 + a] - mu1[a];
            y[a] = G[j * 3 + a] - mu2[a];
        }
        float d0 = scale * (R[0][0]*x[0] + R[0][1]*x[1] + R[0][2]*x[2]) - y[0];
        float d1 = scale * (R[1][0]*x[0] + R[1][1]*x[1] + R[1][2]*x[2]) - y[1];
        float d2 = scale * (R[2][0]*x[0] + R[2][1]*x[1] + R[2][2]*x[2]) - y[2];
        acc += fast_sqrt(d0*d0 + d1*d1 + d2*d2);
    }
    acc = pair_sum(acc);

    if (half == 0 && e < valid)
        out[base + e] = acc * invJ;
}

extern "C" void kernel_launch(void* const* d_in, const int* in_sizes, int n_in,
                              void* d_out, int out_size) {
    const float* pred = (const float*)d_in[0];
    const float* gt   = (const float*)d_in[1];
    float* out = (float*)d_out;
    int B = in_sizes[0] / ELEM;
    int grid = (B + EPB - 1) / EPB;
    pampjpe_kernel<<<grid, TPB>>>(pred, gt, out, B);
}